// round 8
// baseline (speedup 1.0000x reference)
#include <cuda_runtime.h>
#include <cuda_fp16.h>
#include <math.h>

#define B_   128
#define T_   256
#define H_   512
#define G4_  2048   // 4*H

// ---------------- scratch (device globals; no allocation allowed) -------------
// P: input projections, layout [dir][t*B + b][4H]
__device__ float    g_P[134217728];     // 2 * 32768 * 2048
// inter: layer-0 output, layout [dir][t*B + b][H]
__device__ float    g_inter[33554432];  // 2 * 32768 * 512
// h as fp16 mma-A fragments: [pp][dir][slice(32)][warp(8)][lane(32)] uint4
__device__ uint4    g_hfh[32768];       // 512 KB
__device__ unsigned g_arrive[2];        // cumulative, zero-init
__device__ unsigned g_gen[2];           // cumulative, zero-init

// ---------------- helpers ----------------------------------------------------
__device__ __forceinline__ float f2tf(float x) {
    unsigned u;
    asm("cvt.rna.tf32.f32 %0, %1;" : "=r"(u) : "f"(x));
    return __uint_as_float(u);
}

__device__ __forceinline__ void mma8(float* c, const unsigned* a, const unsigned* b) {
    asm volatile(
        "mma.sync.aligned.m16n8k8.row.col.f32.tf32.tf32.f32 "
        "{%0,%1,%2,%3}, {%4,%5,%6,%7}, {%8,%9}, {%0,%1,%2,%3};\n"
        : "+f"(c[0]), "+f"(c[1]), "+f"(c[2]), "+f"(c[3])
        : "r"(a[0]), "r"(a[1]), "r"(a[2]), "r"(a[3]), "r"(b[0]), "r"(b[1]));
}

__device__ __forceinline__ void mma16(float* c, const uint4& a, const uint2& b) {
    asm volatile(
        "mma.sync.aligned.m16n8k16.row.col.f32.f16.f16.f32 "
        "{%0,%1,%2,%3}, {%4,%5,%6,%7}, {%8,%9}, {%0,%1,%2,%3};\n"
        : "+f"(c[0]), "+f"(c[1]), "+f"(c[2]), "+f"(c[3])
        : "r"(a.x), "r"(a.y), "r"(a.z), "r"(a.w), "r"(b.x), "r"(b.y));
}

__device__ __forceinline__ unsigned packh2(float lo, float hi) {
    __half2 h = __halves2half2(__float2half_rn(lo), __float2half_rn(hi));
    return *reinterpret_cast<unsigned*>(&h);
}

__device__ __forceinline__ float sigm(float x) { return 1.f / (1.f + expf(-x)); }

// ---------------- input projection: P = A @ Wx + b ---------------------------
// grid (32, 256, 2): x = N-tile (64 cols), y = t, z = dir.  BM=128 (all of B).
// tf32 mma core (known-good) + reg-staged double buffering.
__global__ void __launch_bounds__(256) xproj_kernel(
    const float* __restrict__ x, const float* __restrict__ Wx,
    const float* __restrict__ bias, int layer, int amode)
{
    __shared__ float As[128][36];
    __shared__ float Bs[32][72];

    const int tid  = threadIdx.x;
    const int dir  = blockIdx.z;
    const int t    = blockIdx.y;
    const int col0 = blockIdx.x * 64;
    const float* W  = Wx   + (size_t)(layer * 2 + dir) * H_ * G4_;
    const float* bs = bias + (layer * 2 + dir) * G4_;
    const float* Ab = amode ? (g_inter + (size_t)dir * 16777216) : x;
    const int lane = tid & 31, warp = tid >> 5;
    const int wm = warp >> 1, wn = warp & 1;

    float acc[2][4][4];
    #pragma unroll
    for (int i = 0; i < 2; i++)
        #pragma unroll
        for (int j = 0; j < 4; j++)
            #pragma unroll
            for (int k = 0; k < 4; k++) acc[i][j][k] = 0.f;

    float4 ra[4], rb[2];

    auto ldA = [&](int kc) {
        #pragma unroll
        for (int i = 0; i < 4; i++) {
            int lin = tid + i * 256;
            int r = lin >> 3, c4 = (lin & 7) << 2;
            const float* src = Ab +
                (amode ? ((size_t)(t * 128 + r)) * 512
                       : ((size_t)(r * 256 + t)) * 512) + kc * 32 + c4;
            ra[i] = *reinterpret_cast<const float4*>(src);
        }
    };
    auto ldB = [&](int kc) {
        #pragma unroll
        for (int i = 0; i < 2; i++) {
            int lin = tid + i * 256;
            int r = lin >> 4, c4 = (lin & 15) << 2;
            rb[i] = *reinterpret_cast<const float4*>(
                W + (size_t)(kc * 32 + r) * G4_ + col0 + c4);
        }
    };

    ldA(0); ldB(0);

    for (int kc = 0; kc < 16; kc++) {
        #pragma unroll
        for (int i = 0; i < 4; i++) {
            int lin = tid + i * 256;
            int r = lin >> 3, c4 = (lin & 7) << 2;
            *reinterpret_cast<float4*>(&As[r][c4]) =
                make_float4(f2tf(ra[i].x), f2tf(ra[i].y), f2tf(ra[i].z), f2tf(ra[i].w));
        }
        #pragma unroll
        for (int i = 0; i < 2; i++) {
            int lin = tid + i * 256;
            int r = lin >> 4, c4 = (lin & 15) << 2;
            *reinterpret_cast<float4*>(&Bs[r][c4]) =
                make_float4(f2tf(rb[i].x), f2tf(rb[i].y), f2tf(rb[i].z), f2tf(rb[i].w));
        }
        __syncthreads();
        if (kc < 15) { ldA(kc + 1); ldB(kc + 1); }   // overlap with mma below
        #pragma unroll
        for (int s = 0; s < 4; s++) {
            int ka = s * 8 + (lane & 3);
            unsigned a[2][4];
            #pragma unroll
            for (int mt = 0; mt < 2; mt++) {
                int r = wm * 32 + mt * 16 + (lane >> 2);
                a[mt][0] = __float_as_uint(As[r][ka]);
                a[mt][1] = __float_as_uint(As[r + 8][ka]);
                a[mt][2] = __float_as_uint(As[r][ka + 4]);
                a[mt][3] = __float_as_uint(As[r + 8][ka + 4]);
            }
            unsigned bf[4][2];
            #pragma unroll
            for (int nt = 0; nt < 4; nt++) {
                int c = wn * 32 + nt * 8 + (lane >> 2);
                bf[nt][0] = __float_as_uint(Bs[s * 8 + (lane & 3)][c]);
                bf[nt][1] = __float_as_uint(Bs[s * 8 + 4 + (lane & 3)][c]);
            }
            #pragma unroll
            for (int mt = 0; mt < 2; mt++)
                #pragma unroll
                for (int nt = 0; nt < 4; nt++)
                    mma8(acc[mt][nt], a[mt], bf[nt]);
        }
        __syncthreads();
    }

    float* Pd = g_P + (size_t)dir * 67108864 + (size_t)t * 128 * 2048;
    #pragma unroll
    for (int nt = 0; nt < 4; nt++) {
        int cg = col0 + wn * 32 + nt * 8 + 2 * (lane & 3);
        float b0 = bs[cg], b1 = bs[cg + 1];
        #pragma unroll
        for (int mt = 0; mt < 2; mt++) {
            int r = wm * 32 + mt * 16 + (lane >> 2);
            *reinterpret_cast<float2*>(Pd + (size_t)r * 2048 + cg) =
                make_float2(acc[mt][nt][0] + b0, acc[mt][nt][1] + b1);
            *reinterpret_cast<float2*>(Pd + (size_t)(r + 8) * 2048 + cg) =
                make_float2(acc[mt][nt][2] + b0, acc[mt][nt][3] + b1);
        }
    }
}

// ---------------- persistent recurrent scan (fp16 mma) ------------------------
// grid (32, 2): 32 blocks/dir. Block owns 16 hidden units = EXACTLY one k16
// slice of the next step's A operand, so the epilogue packs its 8 h values
// straight into an A-fragment uint4 (no smem repack). Warp owns 16 batch rows.
// Wh B-fragments (fp16) prepacked in smem once. c stays fp32 in registers.
#define SCAN_SMEM 65536   // Whb: [32 ks][4 g][2 nt][32 lane] uint2

__global__ void __launch_bounds__(256, 1) scan_kernel(
    const float* __restrict__ Wh_all, int layer, int last, float* __restrict__ out)
{
    extern __shared__ uint2 Whb[];

    const int tid  = threadIdx.x;
    const int lane = tid & 31, warp = tid >> 5;
    const int dir  = blockIdx.y;
    const int slice = blockIdx.x;          // 0..31 -> units j0..j0+15
    const int j0   = slice * 16;
    const float* Wh = Wh_all + (size_t)(layer * 2 + dir) * H_ * G4_;

    __shared__ unsigned s_genbase;
    if (tid == 0) s_genbase = *((volatile unsigned*)&g_gen[dir]);

    // prepack Wh B-fragments (m16n8k16): for (ks,g,nt,lane):
    //   k0 = ks*16 + 2*(lane&3), n = g*512 + j0 + nt*8 + (lane>>2)
    //   b0 = {Wh[k0][n], Wh[k0+1][n]}, b1 = {Wh[k0+8][n], Wh[k0+9][n]}
    for (int idx = tid; idx < 8192; idx += 256) {
        int l  = idx & 31;
        int q  = idx >> 5;                 // 0..255
        int nt = q & 1, g = (q >> 1) & 3, ks = q >> 3;
        int k0 = ks * 16 + 2 * (l & 3);
        int n  = g * 512 + j0 + nt * 8 + (l >> 2);
        unsigned b0 = packh2(Wh[(size_t)k0 * 2048 + n],
                             Wh[(size_t)(k0 + 1) * 2048 + n]);
        unsigned b1 = packh2(Wh[(size_t)(k0 + 8) * 2048 + n],
                             Wh[(size_t)(k0 + 9) * 2048 + n]);
        Whb[idx] = make_uint2(b0, b1);
    }
    __syncthreads();
    const unsigned gen_base = s_genbase;

    const int row_base = warp * 16 + (lane >> 2);
    const int u2 = 2 * (lane & 3);
    float creg[2][4] = {{0.f,0.f,0.f,0.f},{0.f,0.f,0.f,0.f}};
    int p = 0;

    #pragma unroll 1
    for (int s = 0; s < 256; s++) {
        const int t = (dir == 0) ? s : (255 - s);

        // prefetch P (epilogue addend) — DRAM latency hidden under mma loop
        const float* Pp = g_P + (size_t)dir * 67108864 + (size_t)t * 262144;
        float pv[4][2][4];
        #pragma unroll
        for (int g = 0; g < 4; g++)
            #pragma unroll
            for (int nt = 0; nt < 2; nt++) {
                const float* base = Pp + (size_t)row_base * 2048
                                  + g * 512 + j0 + nt * 8 + u2;
                float2 v0 = *reinterpret_cast<const float2*>(base);
                float2 v1 = *reinterpret_cast<const float2*>(base + 8 * 2048);
                pv[g][nt][0] = v0.x; pv[g][nt][1] = v0.y;
                pv[g][nt][2] = v1.x; pv[g][nt][3] = v1.y;
            }

        float acc[4][2][4];
        #pragma unroll
        for (int g = 0; g < 4; g++)
            #pragma unroll
            for (int nt = 0; nt < 2; nt++)
                #pragma unroll
                for (int k = 0; k < 4; k++) acc[g][nt][k] = 0.f;

        if (s > 0) {
            // h @ Wh: 32 k16-slices; A-frags straight from gmem fragment layout
            const uint4* hp = g_hfh + (p * 2 + dir) * 8192 + warp * 32 + lane;
            uint4 buf[2];
            buf[0] = hp[0];
            #pragma unroll 4
            for (int ks = 0; ks < 32; ks++) {
                if (ks < 31) buf[(ks + 1) & 1] = hp[(ks + 1) * 256];
                const uint4 a = buf[ks & 1];
                #pragma unroll
                for (int g = 0; g < 4; g++) {
                    #pragma unroll
                    for (int nt = 0; nt < 2; nt++) {
                        uint2 bb = Whb[((ks * 4 + g) * 2 + nt) * 32 + lane];
                        mma16(acc[g][nt], a, bb);
                    }
                }
            }
        }

        // LSTM pointwise epilogue — all 4 gates for each (b,j) on this thread
        float hn[2][4];
        #pragma unroll
        for (int nt = 0; nt < 2; nt++)
            #pragma unroll
            for (int k = 0; k < 4; k++) {
                float i_ = sigm(acc[0][nt][k] + pv[0][nt][k]);
                float f_ = sigm(acc[1][nt][k] + pv[1][nt][k]);
                float gg = tanhf(acc[2][nt][k] + pv[2][nt][k]);
                float o_ = sigm(acc[3][nt][k] + pv[3][nt][k]);
                float cn = f_ * creg[nt][k] + i_ * gg;
                creg[nt][k] = cn;
                hn[nt][k] = o_ * tanhf(cn);
            }

        // write fp32 outputs (coalesced float2 pairs)
        #pragma unroll
        for (int nt = 0; nt < 2; nt++)
            #pragma unroll
            for (int rr = 0; rr < 2; rr++) {
                int r = row_base + rr * 8;
                int u = j0 + nt * 8 + u2;
                float2 val = make_float2(hn[nt][rr * 2], hn[nt][rr * 2 + 1]);
                if (!last)
                    *reinterpret_cast<float2*>(
                        g_inter + (size_t)dir * 16777216 +
                        ((size_t)t * 128 + r) * 512 + u) = val;
                else
                    *reinterpret_cast<float2*>(
                        out + ((size_t)r * 256 + t) * 1024 + dir * 512 + u) = val;
            }

        if (s < 255) {
            // publish h as next step's A-fragment: layouts align exactly
            uint4 fr;
            fr.x = packh2(hn[0][0], hn[0][1]);
            fr.y = packh2(hn[0][2], hn[0][3]);
            fr.z = packh2(hn[1][0], hn[1][1]);
            fr.w = packh2(hn[1][2], hn[1][3]);
            g_hfh[((1 - p) * 2 + dir) * 8192 + slice * 256 + warp * 32 + lane] = fr;

            // per-direction grid barrier (cumulative counters; load-poll wakeup)
            __syncthreads();
            if (tid == 0) {
                __threadfence();
                unsigned old = atomicAdd(&g_arrive[dir], 1u);
                if ((old & 31u) == 31u) {
                    __threadfence();
                    atomicAdd(&g_gen[dir], 1u);
                } else {
                    unsigned target = gen_base + (unsigned)(s + 1);
                    while ((int)(*((volatile unsigned*)&g_gen[dir]) - target) < 0)
                        __nanosleep(64);
                }
                __threadfence();
            }
            __syncthreads();
        }
        p ^= 1;
    }
}

// ---------------- launch ------------------------------------------------------
extern "C" void kernel_launch(void* const* d_in, const int* in_sizes, int n_in,
                              void* d_out, int out_size)
{
    (void)in_sizes; (void)n_in; (void)out_size;
    const float* x  = (const float*)d_in[0];
    const float* Wx = (const float*)d_in[1];
    const float* Wh = (const float*)d_in[2];
    const float* b  = (const float*)d_in[3];
    float* out = (float*)d_out;

    // idempotent, capture-legal; no static guards (harness rule)
    cudaFuncSetAttribute(scan_kernel,
                         cudaFuncAttributeMaxDynamicSharedMemorySize, SCAN_SMEM);

    dim3 gx(32, 256, 2);
    dim3 gs(32, 2);

    xproj_kernel<<<gx, 256>>>(x, Wx, b, 0, 0);
    scan_kernel<<<gs, 256, SCAN_SMEM>>>(Wh, 0, 0, out);
    xproj_kernel<<<gx, 256>>>(x, Wx, b, 1, 1);
    scan_kernel<<<gs, 256, SCAN_SMEM>>>(Wh, 1, 1, out);
}

// round 10
// speedup vs baseline: 1.1946x; 1.1946x over previous
#include <cuda_runtime.h>
#include <cuda_fp16.h>
#include <math.h>

#define B_   128
#define T_   256
#define H_   512
#define G4_  2048   // 4*H

// ---------------- scratch (device globals; no allocation allowed) -------------
// P: input projections, layout [dir][t*B + b][4H]
__device__ float    g_P[134217728];     // 2 * 32768 * 2048
// inter: layer-0 output, layout [dir][t*B + b][H]
__device__ float    g_inter[33554432];  // 2 * 32768 * 512
// h as fp16 mma-A fragments: [pp][dir][ks(32)][rowtile(8)][lane(32)] uint4
__device__ uint4    g_hfh[32768];       // 512 KB
__device__ unsigned g_arrive[2];        // cumulative, zero-init
__device__ unsigned g_gen[2];           // cumulative, zero-init

// ---------------- helpers ----------------------------------------------------
__device__ __forceinline__ float f2tf(float x) {
    unsigned u;
    asm("cvt.rna.tf32.f32 %0, %1;" : "=r"(u) : "f"(x));
    return __uint_as_float(u);
}

__device__ __forceinline__ void mma8(float* c, const unsigned* a, const unsigned* b) {
    asm volatile(
        "mma.sync.aligned.m16n8k8.row.col.f32.tf32.tf32.f32 "
        "{%0,%1,%2,%3}, {%4,%5,%6,%7}, {%8,%9}, {%0,%1,%2,%3};\n"
        : "+f"(c[0]), "+f"(c[1]), "+f"(c[2]), "+f"(c[3])
        : "r"(a[0]), "r"(a[1]), "r"(a[2]), "r"(a[3]), "r"(b[0]), "r"(b[1]));
}

__device__ __forceinline__ void mma16(float* c, const uint4& a, const uint2& b) {
    asm volatile(
        "mma.sync.aligned.m16n8k16.row.col.f32.f16.f16.f32 "
        "{%0,%1,%2,%3}, {%4,%5,%6,%7}, {%8,%9}, {%0,%1,%2,%3};\n"
        : "+f"(c[0]), "+f"(c[1]), "+f"(c[2]), "+f"(c[3])
        : "r"(a.x), "r"(a.y), "r"(a.z), "r"(a.w), "r"(b.x), "r"(b.y));
}

__device__ __forceinline__ unsigned packh2(float lo, float hi) {
    __half2 h = __halves2half2(__float2half_rn(lo), __float2half_rn(hi));
    return *reinterpret_cast<unsigned*>(&h);
}

__device__ __forceinline__ float sigm(float x) { return 1.f / (1.f + expf(-x)); }

__device__ __forceinline__ void cp_async16(unsigned smem_addr, const void* gptr) {
    asm volatile("cp.async.cg.shared.global [%0], [%1], 16;\n"
                 :: "r"(smem_addr), "l"(gptr));
}
__device__ __forceinline__ void cp_commit() {
    asm volatile("cp.async.commit_group;\n");
}
template<int N> __device__ __forceinline__ void cp_wait() {
    asm volatile("cp.async.wait_group %0;\n" :: "n"(N));
}

// ---------------- input projection: P = A @ Wx + b ---------------------------
// grid (32, 256, 2): x = N-tile (64 cols), y = t, z = dir.  BM=128 (all of B).
// tf32 mma core + reg-staged double buffering; force 2 blocks/SM.
__global__ void __launch_bounds__(256, 2) xproj_kernel(
    const float* __restrict__ x, const float* __restrict__ Wx,
    const float* __restrict__ bias, int layer, int amode)
{
    __shared__ float As[128][36];
    __shared__ float Bs[32][72];

    const int tid  = threadIdx.x;
    const int dir  = blockIdx.z;
    const int t    = blockIdx.y;
    const int col0 = blockIdx.x * 64;
    const float* W  = Wx   + (size_t)(layer * 2 + dir) * H_ * G4_;
    const float* bs = bias + (layer * 2 + dir) * G4_;
    const float* Ab = amode ? (g_inter + (size_t)dir * 16777216) : x;
    const int lane = tid & 31, warp = tid >> 5;
    const int wm = warp >> 1, wn = warp & 1;

    float acc[2][4][4];
    #pragma unroll
    for (int i = 0; i < 2; i++)
        #pragma unroll
        for (int j = 0; j < 4; j++)
            #pragma unroll
            for (int k = 0; k < 4; k++) acc[i][j][k] = 0.f;

    float4 ra[4], rb[2];

    auto ldA = [&](int kc) {
        #pragma unroll
        for (int i = 0; i < 4; i++) {
            int lin = tid + i * 256;
            int r = lin >> 3, c4 = (lin & 7) << 2;
            const float* src = Ab +
                (amode ? ((size_t)(t * 128 + r)) * 512
                       : ((size_t)(r * 256 + t)) * 512) + kc * 32 + c4;
            ra[i] = *reinterpret_cast<const float4*>(src);
        }
    };
    auto ldB = [&](int kc) {
        #pragma unroll
        for (int i = 0; i < 2; i++) {
            int lin = tid + i * 256;
            int r = lin >> 4, c4 = (lin & 15) << 2;
            rb[i] = *reinterpret_cast<const float4*>(
                W + (size_t)(kc * 32 + r) * G4_ + col0 + c4);
        }
    };

    ldA(0); ldB(0);

    for (int kc = 0; kc < 16; kc++) {
        #pragma unroll
        for (int i = 0; i < 4; i++) {
            int lin = tid + i * 256;
            int r = lin >> 3, c4 = (lin & 7) << 2;
            *reinterpret_cast<float4*>(&As[r][c4]) =
                make_float4(f2tf(ra[i].x), f2tf(ra[i].y), f2tf(ra[i].z), f2tf(ra[i].w));
        }
        #pragma unroll
        for (int i = 0; i < 2; i++) {
            int lin = tid + i * 256;
            int r = lin >> 4, c4 = (lin & 15) << 2;
            *reinterpret_cast<float4*>(&Bs[r][c4]) =
                make_float4(f2tf(rb[i].x), f2tf(rb[i].y), f2tf(rb[i].z), f2tf(rb[i].w));
        }
        __syncthreads();
        if (kc < 15) { ldA(kc + 1); ldB(kc + 1); }   // overlap with mma below
        #pragma unroll
        for (int s = 0; s < 4; s++) {
            int ka = s * 8 + (lane & 3);
            unsigned a[2][4];
            #pragma unroll
            for (int mt = 0; mt < 2; mt++) {
                int r = wm * 32 + mt * 16 + (lane >> 2);
                a[mt][0] = __float_as_uint(As[r][ka]);
                a[mt][1] = __float_as_uint(As[r + 8][ka]);
                a[mt][2] = __float_as_uint(As[r][ka + 4]);
                a[mt][3] = __float_as_uint(As[r + 8][ka + 4]);
            }
            unsigned bf[4][2];
            #pragma unroll
            for (int nt = 0; nt < 4; nt++) {
                int c = wn * 32 + nt * 8 + (lane >> 2);
                bf[nt][0] = __float_as_uint(Bs[s * 8 + (lane & 3)][c]);
                bf[nt][1] = __float_as_uint(Bs[s * 8 + 4 + (lane & 3)][c]);
            }
            #pragma unroll
            for (int mt = 0; mt < 2; mt++)
                #pragma unroll
                for (int nt = 0; nt < 4; nt++)
                    mma8(acc[mt][nt], a[mt], bf[nt]);
        }
        __syncthreads();
    }

    float* Pd = g_P + (size_t)dir * 67108864 + (size_t)t * 128 * 2048;
    #pragma unroll
    for (int nt = 0; nt < 4; nt++) {
        int cg = col0 + wn * 32 + nt * 8 + 2 * (lane & 3);
        float b0 = bs[cg], b1 = bs[cg + 1];
        #pragma unroll
        for (int mt = 0; mt < 2; mt++) {
            int r = wm * 32 + mt * 16 + (lane >> 2);
            *reinterpret_cast<float2*>(Pd + (size_t)r * 2048 + cg) =
                make_float2(acc[mt][nt][0] + b0, acc[mt][nt][1] + b1);
            *reinterpret_cast<float2*>(Pd + (size_t)(r + 8) * 2048 + cg) =
                make_float2(acc[mt][nt][2] + b0, acc[mt][nt][3] + b1);
        }
    }
}

// ---------------- persistent recurrent scan (fp16 mma, cp.async h pipe) ------
// grid (32, 2, 2): x = unit-slice (16 units = one k16 slice), y = batch half
// (64 rows), z = dir. 128 blocks -> 128 SMs, 4 warps/block (1/SMSP).
// Warp owns 16 batch rows. h A-fragments flow gmem -> smem via cp.async with
// 4 commit-groups (deep pipeline); each thread consumes exactly the bytes its
// own cp.async wrote (no barrier needed). Wh B-fragments prepacked in smem.
#define SCAN_SMEM (65536 + 65536)   // Whb 64KB + hstage 64KB

__global__ void __launch_bounds__(128, 1) scan_kernel(
    const float* __restrict__ Wh_all, int layer, int last, float* __restrict__ out)
{
    extern __shared__ char smbase[];
    uint2* Whb = reinterpret_cast<uint2*>(smbase);            // [ks][g][nt][lane]
    uint4* hst = reinterpret_cast<uint4*>(smbase + 65536);    // [ks(32)][tid(128)]

    const int tid   = threadIdx.x;
    const int lane  = tid & 31, warp = tid >> 5;    // warp 0..3
    const int slice = blockIdx.x;                   // units j0..j0+15
    const int bhalf = blockIdx.y;                   // batch rows bhalf*64..+63
    const int dir   = blockIdx.z;
    const int j0    = slice * 16;
    const int rt    = bhalf * 4 + warp;             // global m16 row-tile 0..7
    const float* Wh = Wh_all + (size_t)(layer * 2 + dir) * H_ * G4_;

    __shared__ unsigned s_genbase;
    if (tid == 0) s_genbase = *((volatile unsigned*)&g_gen[dir]);

    // prepack Wh B-fragments (m16n8k16), layout [((ks*4+g)*2+nt)*32 + lane]
    for (int idx = tid; idx < 8192; idx += 128) {
        int l  = idx & 31;
        int q  = idx >> 5;
        int nt = q & 1, g = (q >> 1) & 3, ks = q >> 3;
        int k0 = ks * 16 + 2 * (l & 3);
        int n  = g * 512 + j0 + nt * 8 + (l >> 2);
        unsigned b0 = packh2(Wh[(size_t)k0 * 2048 + n],
                             Wh[(size_t)(k0 + 1) * 2048 + n]);
        unsigned b1 = packh2(Wh[(size_t)(k0 + 8) * 2048 + n],
                             Wh[(size_t)(k0 + 9) * 2048 + n]);
        Whb[idx] = make_uint2(b0, b1);
    }
    __syncthreads();
    const unsigned gen_base = s_genbase;

    const int row_base = rt * 16 + (lane >> 2);
    const int u2 = 2 * (lane & 3);
    const unsigned hs_addr =
        (unsigned)__cvta_generic_to_shared(hst) + (unsigned)tid * 16;

    float creg[2][4] = {{0.f,0.f,0.f,0.f},{0.f,0.f,0.f,0.f}};
    float pv[4][2][4];
    int p = 0;

    // prologue: prefetch P for step 0
    {
        const int t0 = (dir == 0) ? 0 : 255;
        const float* Pp = g_P + (size_t)dir * 67108864 + (size_t)t0 * 262144;
        #pragma unroll
        for (int g = 0; g < 4; g++)
            #pragma unroll
            for (int nt = 0; nt < 2; nt++) {
                const float* base = Pp + (size_t)row_base * 2048
                                  + g * 512 + j0 + nt * 8 + u2;
                float2 v0 = *reinterpret_cast<const float2*>(base);
                float2 v1 = *reinterpret_cast<const float2*>(base + 8 * 2048);
                pv[g][nt][0] = v0.x; pv[g][nt][1] = v0.y;
                pv[g][nt][2] = v1.x; pv[g][nt][3] = v1.y;
            }
    }

    #pragma unroll 1
    for (int s = 0; s < 256; s++) {
        const int t = (dir == 0) ? s : (255 - s);

        float acc[4][2][4];
        #pragma unroll
        for (int g = 0; g < 4; g++)
            #pragma unroll
            for (int nt = 0; nt < 2; nt++)
                #pragma unroll
                for (int k = 0; k < 4; k++) acc[g][nt][k] = 0.f;

        if (s > 0) {
            // consume h: 4 groups of 8 k16-slices; staged wait_group pipeline
            #pragma unroll
            for (int grp = 0; grp < 4; grp++) {
                if      (grp == 0) cp_wait<3>();
                else if (grp == 1) cp_wait<2>();
                else if (grp == 2) cp_wait<1>();
                else               cp_wait<0>();
                #pragma unroll
                for (int k8 = 0; k8 < 8; k8++) {
                    int ks = grp * 8 + k8;
                    uint4 a = hst[ks * 128 + tid];     // own cp.async data
                    #pragma unroll
                    for (int g = 0; g < 4; g++)
                        #pragma unroll
                        for (int nt = 0; nt < 2; nt++) {
                            uint2 bb = Whb[((ks * 4 + g) * 2 + nt) * 32 + lane];
                            mma16(acc[g][nt], a, bb);
                        }
                }
            }
        }

        // LSTM pointwise epilogue — all 4 gates for each (b,j) on this thread
        float hn[2][4];
        #pragma unroll
        for (int nt = 0; nt < 2; nt++)
            #pragma unroll
            for (int k = 0; k < 4; k++) {
                float i_ = sigm(acc[0][nt][k] + pv[0][nt][k]);
                float f_ = sigm(acc[1][nt][k] + pv[1][nt][k]);
                float gg = tanhf(acc[2][nt][k] + pv[2][nt][k]);
                float o_ = sigm(acc[3][nt][k] + pv[3][nt][k]);
                float cn = f_ * creg[nt][k] + i_ * gg;
                creg[nt][k] = cn;
                hn[nt][k] = o_ * tanhf(cn);
            }

        // write fp32 outputs (coalesced float2 pairs)
        #pragma unroll
        for (int nt = 0; nt < 2; nt++)
            #pragma unroll
            for (int rr = 0; rr < 2; rr++) {
                int r = row_base + rr * 8;
                int u = j0 + nt * 8 + u2;
                float2 val = make_float2(hn[nt][rr * 2], hn[nt][rr * 2 + 1]);
                if (!last)
                    *reinterpret_cast<float2*>(
                        g_inter + (size_t)dir * 16777216 +
                        ((size_t)t * 128 + r) * 512 + u) = val;
                else
                    *reinterpret_cast<float2*>(
                        out + ((size_t)r * 256 + t) * 1024 + dir * 512 + u) = val;
            }

        if (s < 255) {
            // publish h as next step's A-fragment (layouts align exactly)
            uint4 fr;
            fr.x = packh2(hn[0][0], hn[0][1]);
            fr.y = packh2(hn[0][2], hn[0][3]);
            fr.z = packh2(hn[1][0], hn[1][1]);
            fr.w = packh2(hn[1][2], hn[1][3]);
            g_hfh[((1 - p) * 2 + dir) * 8192 + slice * 256 + rt * 32 + lane] = fr;

            // prefetch P for step s+1 BEFORE the barrier (overlaps the wait)
            {
                const int tn = (dir == 0) ? (s + 1) : (254 - s);
                const float* Pp = g_P + (size_t)dir * 67108864 + (size_t)tn * 262144;
                #pragma unroll
                for (int g = 0; g < 4; g++)
                    #pragma unroll
                    for (int nt = 0; nt < 2; nt++) {
                        const float* base = Pp + (size_t)row_base * 2048
                                          + g * 512 + j0 + nt * 8 + u2;
                        float2 v0 = *reinterpret_cast<const float2*>(base);
                        float2 v1 = *reinterpret_cast<const float2*>(base + 8 * 2048);
                        pv[g][nt][0] = v0.x; pv[g][nt][1] = v0.y;
                        pv[g][nt][2] = v1.x; pv[g][nt][3] = v1.y;
                    }
            }

            // per-direction grid barrier (64 blocks; cumulative counters)
            __syncthreads();
            if (tid == 0) {
                __threadfence();
                unsigned old = atomicAdd(&g_arrive[dir], 1u);
                if ((old & 63u) == 63u) {
                    __threadfence();
                    atomicAdd(&g_gen[dir], 1u);
                } else {
                    unsigned target = gen_base + (unsigned)(s + 1);
                    while ((int)(*((volatile unsigned*)&g_gen[dir]) - target) < 0) {}
                }
                __threadfence();
            }
            __syncthreads();

            // issue next step's h loads: 32 slices, 4 commit groups
            const uint4* hsrc = g_hfh + ((1 - p) * 2 + dir) * 8192
                              + bhalf * 128 + tid;
            #pragma unroll
            for (int grp = 0; grp < 4; grp++) {
                #pragma unroll
                for (int k8 = 0; k8 < 8; k8++) {
                    int ks = grp * 8 + k8;
                    cp_async16(hs_addr + (unsigned)ks * 2048, hsrc + ks * 256);
                }
                cp_commit();
            }
        }
        p ^= 1;
    }
}

// ---------------- launch ------------------------------------------------------
extern "C" void kernel_launch(void* const* d_in, const int* in_sizes, int n_in,
                              void* d_out, int out_size)
{
    (void)in_sizes; (void)n_in; (void)out_size;
    const float* x  = (const float*)d_in[0];
    const float* Wx = (const float*)d_in[1];
    const float* Wh = (const float*)d_in[2];
    const float* b  = (const float*)d_in[3];
    float* out = (float*)d_out;

    // idempotent, capture-legal; no static guards (harness rule)
    cudaFuncSetAttribute(scan_kernel,
                         cudaFuncAttributeMaxDynamicSharedMemorySize, SCAN_SMEM);

    dim3 gx(32, 256, 2);
    dim3 gs(32, 2, 2);

    xproj_kernel<<<gx, 256>>>(x, Wx, b, 0, 0);
    scan_kernel<<<gs, 128, SCAN_SMEM>>>(Wh, 0, 0, out);
    xproj_kernel<<<gx, 256>>>(x, Wx, b, 1, 1);
    scan_kernel<<<gs, 128, SCAN_SMEM>>>(Wh, 1, 1, out);
}

// round 12
// speedup vs baseline: 1.2571x; 1.0523x over previous
#include <cuda_runtime.h>
#include <cuda_fp16.h>
#include <math.h>

#define B_   128
#define T_   256
#define H_   512
#define G4_  2048   // 4*H

// ---------------- scratch (device globals; no allocation allowed) -------------
// P: input projections, layout [dir][t*B + b][4H]
__device__ float    g_P[134217728];     // 2 * 32768 * 2048
// inter: layer-0 output, layout [dir][t*B + b][H]
__device__ float    g_inter[33554432];  // 2 * 32768 * 512
// h as fp16 mma-A fragments: [pp][dir][ks(32)][rowtile(8)][lane(32)] uint4
__device__ uint4    g_hfh[32768];       // 512 KB
__device__ unsigned g_arrive[4];        // cumulative, zero-init  [dir*2+bhalf]
__device__ unsigned g_gen[4];           // cumulative, zero-init

// ---------------- helpers ----------------------------------------------------
__device__ __forceinline__ float f2tf(float x) {
    unsigned u;
    asm("cvt.rna.tf32.f32 %0, %1;" : "=r"(u) : "f"(x));
    return __uint_as_float(u);
}

__device__ __forceinline__ void mma8(float* c, const unsigned* a, const unsigned* b) {
    asm volatile(
        "mma.sync.aligned.m16n8k8.row.col.f32.tf32.tf32.f32 "
        "{%0,%1,%2,%3}, {%4,%5,%6,%7}, {%8,%9}, {%0,%1,%2,%3};\n"
        : "+f"(c[0]), "+f"(c[1]), "+f"(c[2]), "+f"(c[3])
        : "r"(a[0]), "r"(a[1]), "r"(a[2]), "r"(a[3]), "r"(b[0]), "r"(b[1]));
}

__device__ __forceinline__ void mma16(float* c, const uint4& a, const uint2& b) {
    asm volatile(
        "mma.sync.aligned.m16n8k16.row.col.f32.f16.f16.f32 "
        "{%0,%1,%2,%3}, {%4,%5,%6,%7}, {%8,%9}, {%0,%1,%2,%3};\n"
        : "+f"(c[0]), "+f"(c[1]), "+f"(c[2]), "+f"(c[3])
        : "r"(a.x), "r"(a.y), "r"(a.z), "r"(a.w), "r"(b.x), "r"(b.y));
}

__device__ __forceinline__ unsigned packh2(float lo, float hi) {
    __half2 h = __halves2half2(__float2half_rn(lo), __float2half_rn(hi));
    return *reinterpret_cast<unsigned*>(&h);
}

__device__ __forceinline__ float sigm(float x) { return 1.f / (1.f + expf(-x)); }

__device__ __forceinline__ void cp_async16(unsigned smem_addr, const void* gptr) {
    asm volatile("cp.async.cg.shared.global [%0], [%1], 16;\n"
                 :: "r"(smem_addr), "l"(gptr));
}
__device__ __forceinline__ void cp_commit() {
    asm volatile("cp.async.commit_group;\n");
}
template<int N> __device__ __forceinline__ void cp_wait() {
    asm volatile("cp.async.wait_group %0;\n" :: "n"(N));
}

// ---------------- input projection: P = A @ Wx + b ---------------------------
// grid (16, 256, 2): x = N-tile (128 cols), y = t, z = dir.  BM=128 (all of B).
// tf32 mma, 128x128 block tile, warp tile 32x64, reg-staged double buffering.
__global__ void __launch_bounds__(256) xproj_kernel(
    const float* __restrict__ x, const float* __restrict__ Wx,
    const float* __restrict__ bias, int layer, int amode)
{
    __shared__ float As[128][36];    // pad 36: A-frag LDS conflict-free
    __shared__ float Bs[32][136];    // pad 136 (8 mod 32): B-frag conflict-free

    const int tid  = threadIdx.x;
    const int dir  = blockIdx.z;
    const int t    = blockIdx.y;
    const int col0 = blockIdx.x * 128;
    const float* W  = Wx   + (size_t)(layer * 2 + dir) * H_ * G4_;
    const float* bs = bias + (layer * 2 + dir) * G4_;
    const float* Ab = amode ? (g_inter + (size_t)dir * 16777216) : x;
    const int lane = tid & 31, warp = tid >> 5;
    const int wm = warp >> 1, wn = warp & 1;   // 4x2 warps, warp tile 32x64

    float acc[2][8][4];
    #pragma unroll
    for (int i = 0; i < 2; i++)
        #pragma unroll
        for (int j = 0; j < 8; j++)
            #pragma unroll
            for (int k = 0; k < 4; k++) acc[i][j][k] = 0.f;

    float4 ra[4], rb[4];

    auto ldA = [&](int kc) {
        #pragma unroll
        for (int i = 0; i < 4; i++) {
            int lin = tid + i * 256;
            int r = lin >> 3, c4 = (lin & 7) << 2;
            const float* src = Ab +
                (amode ? ((size_t)(t * 128 + r)) * 512
                       : ((size_t)(r * 256 + t)) * 512) + kc * 32 + c4;
            ra[i] = *reinterpret_cast<const float4*>(src);
        }
    };
    auto ldB = [&](int kc) {
        #pragma unroll
        for (int i = 0; i < 4; i++) {
            int lin = tid + i * 256;
            int r = lin >> 5, c4 = (lin & 31) << 2;
            rb[i] = *reinterpret_cast<const float4*>(
                W + (size_t)(kc * 32 + r) * G4_ + col0 + c4);
        }
    };

    ldA(0); ldB(0);

    for (int kc = 0; kc < 16; kc++) {
        #pragma unroll
        for (int i = 0; i < 4; i++) {
            int lin = tid + i * 256;
            int r = lin >> 3, c4 = (lin & 7) << 2;
            *reinterpret_cast<float4*>(&As[r][c4]) =
                make_float4(f2tf(ra[i].x), f2tf(ra[i].y), f2tf(ra[i].z), f2tf(ra[i].w));
        }
        #pragma unroll
        for (int i = 0; i < 4; i++) {
            int lin = tid + i * 256;
            int r = lin >> 5, c4 = (lin & 31) << 2;
            *reinterpret_cast<float4*>(&Bs[r][c4]) =
                make_float4(f2tf(rb[i].x), f2tf(rb[i].y), f2tf(rb[i].z), f2tf(rb[i].w));
        }
        __syncthreads();
        if (kc < 15) { ldA(kc + 1); ldB(kc + 1); }   // overlap with mma below
        #pragma unroll
        for (int s = 0; s < 4; s++) {
            int ka = s * 8 + (lane & 3);
            unsigned a[2][4];
            #pragma unroll
            for (int mt = 0; mt < 2; mt++) {
                int r = wm * 32 + mt * 16 + (lane >> 2);
                a[mt][0] = __float_as_uint(As[r][ka]);
                a[mt][1] = __float_as_uint(As[r + 8][ka]);
                a[mt][2] = __float_as_uint(As[r][ka + 4]);
                a[mt][3] = __float_as_uint(As[r + 8][ka + 4]);
            }
            #pragma unroll
            for (int nt = 0; nt < 8; nt++) {
                int c = wn * 64 + nt * 8 + (lane >> 2);
                unsigned bf[2];
                bf[0] = __float_as_uint(Bs[s * 8 + (lane & 3)][c]);
                bf[1] = __float_as_uint(Bs[s * 8 + 4 + (lane & 3)][c]);
                #pragma unroll
                for (int mt = 0; mt < 2; mt++)
                    mma8(acc[mt][nt], a[mt], bf);
            }
        }
        __syncthreads();
    }

    float* Pd = g_P + (size_t)dir * 67108864 + (size_t)t * 128 * 2048;
    #pragma unroll
    for (int nt = 0; nt < 8; nt++) {
        int cg = col0 + wn * 64 + nt * 8 + 2 * (lane & 3);
        float b0 = bs[cg], b1 = bs[cg + 1];
        #pragma unroll
        for (int mt = 0; mt < 2; mt++) {
            int r = wm * 32 + mt * 16 + (lane >> 2);
            *reinterpret_cast<float2*>(Pd + (size_t)r * 2048 + cg) =
                make_float2(acc[mt][nt][0] + b0, acc[mt][nt][1] + b1);
            *reinterpret_cast<float2*>(Pd + (size_t)(r + 8) * 2048 + cg) =
                make_float2(acc[mt][nt][2] + b0, acc[mt][nt][3] + b1);
        }
    }
}

// ---------------- persistent recurrent scan (fp16 mma, cp.async h pipe) ------
// grid (32, 2, 2): x = unit-slice (16 units = one k16 slice), y = batch half
// (64 rows), z = dir. 128 blocks -> 128 SMs, 4 warps/block (1/SMSP).
// Batch halves never communicate -> barrier per (dir,bhalf): fan-in 32.
#define SCAN_SMEM (65536 + 65536)   // Whb 64KB + hstage 64KB

__global__ void __launch_bounds__(128, 1) scan_kernel(
    const float* __restrict__ Wh_all, int layer, int last, float* __restrict__ out)
{
    extern __shared__ char smbase[];
    uint2* Whb = reinterpret_cast<uint2*>(smbase);            // [ks][g][nt][lane]
    uint4* hst = reinterpret_cast<uint4*>(smbase + 65536);    // [ks(32)][tid(128)]

    const int tid   = threadIdx.x;
    const int lane  = tid & 31, warp = tid >> 5;    // warp 0..3
    const int slice = blockIdx.x;                   // units j0..j0+15
    const int bhalf = blockIdx.y;                   // batch rows bhalf*64..+63
    const int dir   = blockIdx.z;
    const int grp   = dir * 2 + bhalf;              // barrier group (32 blocks)
    const int j0    = slice * 16;
    const int rt    = bhalf * 4 + warp;             // global m16 row-tile 0..7
    const float* Wh = Wh_all + (size_t)(layer * 2 + dir) * H_ * G4_;

    __shared__ unsigned s_genbase;
    if (tid == 0) s_genbase = *((volatile unsigned*)&g_gen[grp]);

    // prepack Wh B-fragments (m16n8k16), layout [((ks*4+g)*2+nt)*32 + lane]
    for (int idx = tid; idx < 8192; idx += 128) {
        int l  = idx & 31;
        int q  = idx >> 5;
        int nt = q & 1, g = (q >> 1) & 3, ks = q >> 3;
        int k0 = ks * 16 + 2 * (l & 3);
        int n  = g * 512 + j0 + nt * 8 + (l >> 2);
        unsigned b0 = packh2(Wh[(size_t)k0 * 2048 + n],
                             Wh[(size_t)(k0 + 1) * 2048 + n]);
        unsigned b1 = packh2(Wh[(size_t)(k0 + 8) * 2048 + n],
                             Wh[(size_t)(k0 + 9) * 2048 + n]);
        Whb[idx] = make_uint2(b0, b1);
    }
    __syncthreads();
    const unsigned gen_base = s_genbase;

    const int row_base = rt * 16 + (lane >> 2);
    const int u2 = 2 * (lane & 3);
    const unsigned hs_addr =
        (unsigned)__cvta_generic_to_shared(hst) + (unsigned)tid * 16;

    float creg[2][4] = {{0.f,0.f,0.f,0.f},{0.f,0.f,0.f,0.f}};
    float pv[4][2][4];
    int p = 0;

    // prologue: prefetch P for step 0
    {
        const int t0 = (dir == 0) ? 0 : 255;
        const float* Pp = g_P + (size_t)dir * 67108864 + (size_t)t0 * 262144;
        #pragma unroll
        for (int g = 0; g < 4; g++)
            #pragma unroll
            for (int nt = 0; nt < 2; nt++) {
                const float* base = Pp + (size_t)row_base * 2048
                                  + g * 512 + j0 + nt * 8 + u2;
                float2 v0 = *reinterpret_cast<const float2*>(base);
                float2 v1 = *reinterpret_cast<const float2*>(base + 8 * 2048);
                pv[g][nt][0] = v0.x; pv[g][nt][1] = v0.y;
                pv[g][nt][2] = v1.x; pv[g][nt][3] = v1.y;
            }
    }

    #pragma unroll 1
    for (int s = 0; s < 256; s++) {
        const int t = (dir == 0) ? s : (255 - s);

        float acc[4][2][4];
        #pragma unroll
        for (int g = 0; g < 4; g++)
            #pragma unroll
            for (int nt = 0; nt < 2; nt++)
                #pragma unroll
                for (int k = 0; k < 4; k++) acc[g][nt][k] = 0.f;

        if (s > 0) {
            // consume h: 4 groups of 8 k16-slices; staged wait_group pipeline
            #pragma unroll
            for (int grp4 = 0; grp4 < 4; grp4++) {
                if      (grp4 == 0) cp_wait<3>();
                else if (grp4 == 1) cp_wait<2>();
                else if (grp4 == 2) cp_wait<1>();
                else                cp_wait<0>();
                #pragma unroll
                for (int k8 = 0; k8 < 8; k8++) {
                    int ks = grp4 * 8 + k8;
                    uint4 a = hst[ks * 128 + tid];     // own cp.async data
                    #pragma unroll
                    for (int g = 0; g < 4; g++)
                        #pragma unroll
                        for (int nt = 0; nt < 2; nt++) {
                            uint2 bb = Whb[((ks * 4 + g) * 2 + nt) * 32 + lane];
                            mma16(acc[g][nt], a, bb);
                        }
                }
            }
        }

        // LSTM pointwise epilogue — all 4 gates for each (b,j) on this thread
        float hn[2][4];
        #pragma unroll
        for (int nt = 0; nt < 2; nt++)
            #pragma unroll
            for (int k = 0; k < 4; k++) {
                float i_ = sigm(acc[0][nt][k] + pv[0][nt][k]);
                float f_ = sigm(acc[1][nt][k] + pv[1][nt][k]);
                float gg = tanhf(acc[2][nt][k] + pv[2][nt][k]);
                float o_ = sigm(acc[3][nt][k] + pv[3][nt][k]);
                float cn = f_ * creg[nt][k] + i_ * gg;
                creg[nt][k] = cn;
                hn[nt][k] = o_ * tanhf(cn);
            }

        // publish h FIRST (shortens producer->consumer chain)
        if (s < 255) {
            uint4 fr;
            fr.x = packh2(hn[0][0], hn[0][1]);
            fr.y = packh2(hn[0][2], hn[0][3]);
            fr.z = packh2(hn[1][0], hn[1][1]);
            fr.w = packh2(hn[1][2], hn[1][3]);
            g_hfh[((1 - p) * 2 + dir) * 8192 + slice * 256 + rt * 32 + lane] = fr;
        }

        // write fp32 outputs (coalesced float2 pairs)
        #pragma unroll
        for (int nt = 0; nt < 2; nt++)
            #pragma unroll
            for (int rr = 0; rr < 2; rr++) {
                int r = row_base + rr * 8;
                int u = j0 + nt * 8 + u2;
                float2 val = make_float2(hn[nt][rr * 2], hn[nt][rr * 2 + 1]);
                if (!last)
                    *reinterpret_cast<float2*>(
                        g_inter + (size_t)dir * 16777216 +
                        ((size_t)t * 128 + r) * 512 + u) = val;
                else
                    *reinterpret_cast<float2*>(
                        out + ((size_t)r * 256 + t) * 1024 + dir * 512 + u) = val;
            }

        if (s < 255) {
            // prefetch P for step s+1 BEFORE the barrier (overlaps the wait)
            {
                const int tn = (dir == 0) ? (s + 1) : (254 - s);
                const float* Pp = g_P + (size_t)dir * 67108864 + (size_t)tn * 262144;
                #pragma unroll
                for (int g = 0; g < 4; g++)
                    #pragma unroll
                    for (int nt = 0; nt < 2; nt++) {
                        const float* base = Pp + (size_t)row_base * 2048
                                          + g * 512 + j0 + nt * 8 + u2;
                        float2 v0 = *reinterpret_cast<const float2*>(base);
                        float2 v1 = *reinterpret_cast<const float2*>(base + 8 * 2048);
                        pv[g][nt][0] = v0.x; pv[g][nt][1] = v0.y;
                        pv[g][nt][2] = v1.x; pv[g][nt][3] = v1.y;
                    }
            }

            // per-(dir,bhalf) grid barrier (32 blocks; cumulative counters)
            __syncthreads();
            if (tid == 0) {
                __threadfence();
                unsigned old = atomicAdd(&g_arrive[grp], 1u);
                if ((old & 31u) == 31u) {
                    __threadfence();
                    atomicAdd(&g_gen[grp], 1u);
                } else {
                    unsigned target = gen_base + (unsigned)(s + 1);
                    while ((int)(*((volatile unsigned*)&g_gen[grp]) - target) < 0) {}
                }
                __threadfence();
            }
            __syncthreads();

            // issue next step's h loads: 32 slices, 4 commit groups
            const uint4* hsrc = g_hfh + ((1 - p) * 2 + dir) * 8192
                              + bhalf * 128 + tid;
            #pragma unroll
            for (int grp4 = 0; grp4 < 4; grp4++) {
                #pragma unroll
                for (int k8 = 0; k8 < 8; k8++) {
                    int ks = grp4 * 8 + k8;
                    cp_async16(hs_addr + (unsigned)ks * 2048, hsrc + ks * 256);
                }
                cp_commit();
            }
        }
        p ^= 1;
    }
}

// ---------------- launch ------------------------------------------------------
extern "C" void kernel_launch(void* const* d_in, const int* in_sizes, int n_in,
                              void* d_out, int out_size)
{
    (void)in_sizes; (void)n_in; (void)out_size;
    const float* x  = (const float*)d_in[0];
    const float* Wx = (const float*)d_in[1];
    const float* Wh = (const float*)d_in[2];
    const float* b  = (const float*)d_in[3];
    float* out = (float*)d_out;

    // idempotent, capture-legal; no static guards (harness rule)
    cudaFuncSetAttribute(scan_kernel,
                         cudaFuncAttributeMaxDynamicSharedMemorySize, SCAN_SMEM);

    dim3 gx(16, 256, 2);
    dim3 gs(32, 2, 2);

    xproj_kernel<<<gx, 256>>>(x, Wx, b, 0, 0);
    scan_kernel<<<gs, 128, SCAN_SMEM>>>(Wh, 0, 0, out);
    xproj_kernel<<<gx, 256>>>(x, Wx, b, 1, 1);
    scan_kernel<<<gs, 128, SCAN_SMEM>>>(Wh, 1, 1, out);
}

// round 13
// speedup vs baseline: 1.2731x; 1.0128x over previous
#include <cuda_runtime.h>
#include <cuda_fp16.h>
#include <math.h>

#define B_   128
#define T_   256
#define H_   512
#define G4_  2048   // 4*H

// ---------------- scratch (device globals; no allocation allowed) -------------
// x as fp16 mma-A fragments: [t(256)][ks(32)][rt(8)][lane(32)] uint4  (33.5 MB)
__device__ uint4    g_xf[2097152];
// layer-0 output as fragments: [dir][t][ks][rt][lane] uint4           (67 MB)
__device__ uint4    g_if[4194304];
// h ping-pong as fp16 mma-A fragments: [pp][dir][ks(32)][rt(8)][lane(32)]
__device__ uint4    g_hfh[32768];       // 512 KB
__device__ unsigned g_arrive[4];        // cumulative, zero-init  [dir*2+bhalf]
__device__ unsigned g_gen[4];           // cumulative, zero-init

// ---------------- helpers ----------------------------------------------------
__device__ __forceinline__ void mma16(float* c, const uint4& a, const uint2& b) {
    asm volatile(
        "mma.sync.aligned.m16n8k16.row.col.f32.f16.f16.f32 "
        "{%0,%1,%2,%3}, {%4,%5,%6,%7}, {%8,%9}, {%0,%1,%2,%3};\n"
        : "+f"(c[0]), "+f"(c[1]), "+f"(c[2]), "+f"(c[3])
        : "r"(a.x), "r"(a.y), "r"(a.z), "r"(a.w), "r"(b.x), "r"(b.y));
}

__device__ __forceinline__ unsigned packh2(float lo, float hi) {
    __half2 h = __halves2half2(__float2half_rn(lo), __float2half_rn(hi));
    return *reinterpret_cast<unsigned*>(&h);
}

__device__ __forceinline__ float sigm(float x) {
    return 1.f / (1.f + __expf(-x));      // MUFU.EX2 + MUFU.RCP, ~1e-7 rel err
}
__device__ __forceinline__ float tanh_(float x) {
    float e = __expf(2.f * x);            // inf-safe: x>>0 -> 1, x<<0 -> -1
    return 1.f - 2.f / (e + 1.f);
}

__device__ __forceinline__ void cp_async16(unsigned smem_addr, const void* gptr) {
    asm volatile("cp.async.cg.shared.global [%0], [%1], 16;\n"
                 :: "r"(smem_addr), "l"(gptr));
}
__device__ __forceinline__ void cp_commit() {
    asm volatile("cp.async.commit_group;\n");
}
template<int N> __device__ __forceinline__ void cp_wait() {
    asm volatile("cp.async.wait_group %0;\n" :: "n"(N));
}

// ---------------- x -> fp16 A-fragment conversion -----------------------------
// grid (256, 2) x 128 threads: t = bx, bhalf = by, rt = bhalf*4 + warp.
// Fragment map identical to the (validated) h-publish layout.
__global__ void __launch_bounds__(128) conv_kernel(const float* __restrict__ x)
{
    const int t = blockIdx.x, bhalf = blockIdx.y;
    const int tid = threadIdx.x, lane = tid & 31, warp = tid >> 5;
    const int rt = bhalf * 4 + warp;
    const int r  = rt * 16 + (lane >> 2);
    const int k0 = 2 * (lane & 3);
    const float* xr0 = x + ((size_t)r * 256 + t) * 512;
    const float* xr1 = x + ((size_t)(r + 8) * 256 + t) * 512;
    uint4* dst = g_xf + (size_t)t * 8192 + rt * 32 + lane;
    #pragma unroll 4
    for (int ks = 0; ks < 32; ks++) {
        int kk = ks * 16 + k0;
        float2 a0 = *reinterpret_cast<const float2*>(xr0 + kk);
        float2 a1 = *reinterpret_cast<const float2*>(xr1 + kk);
        float2 a2 = *reinterpret_cast<const float2*>(xr0 + kk + 8);
        float2 a3 = *reinterpret_cast<const float2*>(xr1 + kk + 8);
        uint4 fr;
        fr.x = packh2(a0.x, a0.y);
        fr.y = packh2(a1.x, a1.y);
        fr.z = packh2(a2.x, a2.y);
        fr.w = packh2(a3.x, a3.y);
        dst[ks * 256] = fr;
    }
}

// ---------------- fused persistent scan (recurrence + input projection) ------
// grid (32, 2, 2): x = unit-slice (16 units = one k16 slice), y = batch half,
// z = dir. 128 blocks -> 128 SMs, 4 warps (1/SMSP). Per step:
//   h-mma (cp.async pipe) -> epilogue -> publish -> arrive ->
//   xp(t+1) = bias + x_{t+1} @ Wx   [overlaps the barrier wait] -> poll -> next
// smem: Whb 64K + Wxb 64K + hstage 64K = 192 KB.
#define SCAN_SMEM (65536 + 65536 + 65536)

__global__ void __launch_bounds__(128, 1) scan_kernel(
    const float* __restrict__ Wh_all, const float* __restrict__ Wx_all,
    const float* __restrict__ bias, int layer, int last, float* __restrict__ out)
{
    extern __shared__ char smbase[];
    uint2* Whb = reinterpret_cast<uint2*>(smbase);             // [((ks*4+g)*2+nt)*32+l]
    uint2* Wxb = reinterpret_cast<uint2*>(smbase + 65536);
    uint4* hst = reinterpret_cast<uint4*>(smbase + 131072);    // [ks(32)][tid(128)]

    const int tid   = threadIdx.x;
    const int lane  = tid & 31, warp = tid >> 5;
    const int slice = blockIdx.x;
    const int bhalf = blockIdx.y;
    const int dir   = blockIdx.z;
    const int grp   = dir * 2 + bhalf;
    const int j0    = slice * 16;
    const int rt    = bhalf * 4 + warp;
    const float* Wh = Wh_all + (size_t)(layer * 2 + dir) * H_ * G4_;
    const float* Wx = Wx_all + (size_t)(layer * 2 + dir) * H_ * G4_;
    const float* bs = bias   + (layer * 2 + dir) * G4_;
    const uint4* xfrag = layer ? (g_if + (size_t)dir * 2097152) : g_xf;

    __shared__ unsigned s_genbase;
    if (tid == 0) s_genbase = *((volatile unsigned*)&g_gen[grp]);

    // prepack Wh and Wx B-fragments (m16n8k16)
    for (int idx = tid; idx < 8192; idx += 128) {
        int l  = idx & 31;
        int q  = idx >> 5;
        int nt = q & 1, g = (q >> 1) & 3, ks = q >> 3;
        int k0 = ks * 16 + 2 * (l & 3);
        int n  = g * 512 + j0 + nt * 8 + (l >> 2);
        Whb[idx] = make_uint2(
            packh2(Wh[(size_t)k0 * 2048 + n], Wh[(size_t)(k0 + 1) * 2048 + n]),
            packh2(Wh[(size_t)(k0 + 8) * 2048 + n], Wh[(size_t)(k0 + 9) * 2048 + n]));
        Wxb[idx] = make_uint2(
            packh2(Wx[(size_t)k0 * 2048 + n], Wx[(size_t)(k0 + 1) * 2048 + n]),
            packh2(Wx[(size_t)(k0 + 8) * 2048 + n], Wx[(size_t)(k0 + 9) * 2048 + n]));
    }
    __syncthreads();
    const unsigned gen_base = s_genbase;

    const int row_base = rt * 16 + (lane >> 2);
    const int u2 = 2 * (lane & 3);
    const unsigned hs_addr =
        (unsigned)__cvta_generic_to_shared(hst) + (unsigned)tid * 16;

    // bias per (g, nt), cols u2/u2+1
    float2 bias2[4][2];
    #pragma unroll
    for (int g = 0; g < 4; g++)
        #pragma unroll
        for (int nt = 0; nt < 2; nt++)
            bias2[g][nt] = *reinterpret_cast<const float2*>(
                bs + g * 512 + j0 + nt * 8 + u2);

    float creg[2][4] = {{0.f,0.f,0.f,0.f},{0.f,0.f,0.f,0.f}};
    float pvacc[4][2][4];
    int p = 0;

    // xp phase: pvacc = bias + x_tn @ Wx  (depth-8 LDG register pipeline)
    auto xphase = [&](int tn) {
        const uint4* xs = xfrag + (size_t)tn * 8192 + rt * 32 + lane;
        uint4 xb[8];
        #pragma unroll
        for (int i = 0; i < 8; i++) xb[i] = xs[i * 256];
        #pragma unroll
        for (int g = 0; g < 4; g++)
            #pragma unroll
            for (int nt = 0; nt < 2; nt++) {
                pvacc[g][nt][0] = bias2[g][nt].x;
                pvacc[g][nt][1] = bias2[g][nt].y;
                pvacc[g][nt][2] = bias2[g][nt].x;
                pvacc[g][nt][3] = bias2[g][nt].y;
            }
        #pragma unroll
        for (int ks = 0; ks < 32; ks++) {
            uint4 a = xb[ks & 7];
            if (ks < 24) xb[ks & 7] = xs[(ks + 8) * 256];
            #pragma unroll
            for (int g = 0; g < 4; g++)
                #pragma unroll
                for (int nt = 0; nt < 2; nt++)
                    mma16(pvacc[g][nt], a, Wxb[((ks * 4 + g) * 2 + nt) * 32 + lane]);
        }
    };

    // prologue: xp for step 0
    xphase((dir == 0) ? 0 : 255);

    #pragma unroll 1
    for (int s = 0; s < 256; s++) {
        const int t = (dir == 0) ? s : (255 - s);

        float acc[4][2][4];
        #pragma unroll
        for (int g = 0; g < 4; g++)
            #pragma unroll
            for (int nt = 0; nt < 2; nt++)
                #pragma unroll
                for (int k = 0; k < 4; k++) acc[g][nt][k] = 0.f;

        if (s > 0) {
            // consume h: 4 groups of 8 k16-slices; staged wait_group pipeline
            #pragma unroll
            for (int g4 = 0; g4 < 4; g4++) {
                if      (g4 == 0) cp_wait<3>();
                else if (g4 == 1) cp_wait<2>();
                else if (g4 == 2) cp_wait<1>();
                else              cp_wait<0>();
                #pragma unroll
                for (int k8 = 0; k8 < 8; k8++) {
                    int ks = g4 * 8 + k8;
                    uint4 a = hst[ks * 128 + tid];
                    #pragma unroll
                    for (int g = 0; g < 4; g++)
                        #pragma unroll
                        for (int nt = 0; nt < 2; nt++)
                            mma16(acc[g][nt], a,
                                  Whb[((ks * 4 + g) * 2 + nt) * 32 + lane]);
                }
            }
        }

        // LSTM pointwise epilogue (gates = h-mma + xp)
        float hn[2][4];
        #pragma unroll
        for (int nt = 0; nt < 2; nt++)
            #pragma unroll
            for (int k = 0; k < 4; k++) {
                float i_ = sigm(acc[0][nt][k] + pvacc[0][nt][k]);
                float f_ = sigm(acc[1][nt][k] + pvacc[1][nt][k]);
                float gg = tanh_(acc[2][nt][k] + pvacc[2][nt][k]);
                float o_ = sigm(acc[3][nt][k] + pvacc[3][nt][k]);
                float cn = f_ * creg[nt][k] + i_ * gg;
                creg[nt][k] = cn;
                hn[nt][k] = o_ * tanh_(cn);
            }

        // h in A-fragment form (validated layout)
        uint4 fr;
        fr.x = packh2(hn[0][0], hn[0][1]);
        fr.y = packh2(hn[0][2], hn[0][3]);
        fr.z = packh2(hn[1][0], hn[1][1]);
        fr.w = packh2(hn[1][2], hn[1][3]);

        if (s < 255)   // publish for next step's consumers
            g_hfh[((1 - p) * 2 + dir) * 8192 + slice * 256 + rt * 32 + lane] = fr;

        if (!last) {   // layer-0: record fragments for layer-1 input
            g_if[(size_t)dir * 2097152 + (size_t)t * 8192
                 + slice * 256 + rt * 32 + lane] = fr;
        } else {       // layer-1: final fp32 output
            #pragma unroll
            for (int nt = 0; nt < 2; nt++)
                #pragma unroll
                for (int rr = 0; rr < 2; rr++) {
                    int r = row_base + rr * 8;
                    int u = j0 + nt * 8 + u2;
                    *reinterpret_cast<float2*>(
                        out + ((size_t)r * 256 + t) * 1024 + dir * 512 + u) =
                        make_float2(hn[nt][rr * 2], hn[nt][rr * 2 + 1]);
                }
        }

        if (s < 255) {
            // arrive (leader bumps gen); then overlap xp(t+1) with the wait
            __syncthreads();
            if (tid == 0) {
                __threadfence();
                unsigned old = atomicAdd(&g_arrive[grp], 1u);
                if ((old & 31u) == 31u) {
                    __threadfence();
                    atomicAdd(&g_gen[grp], 1u);
                }
            }

            xphase((dir == 0) ? (s + 1) : (254 - s));   // fills the barrier wait

            // all threads poll (no post-wake syncthreads: warps independent)
            {
                unsigned target = gen_base + (unsigned)(s + 1);
                while ((int)(*((volatile unsigned*)&g_gen[grp]) - target) < 0) {}
            }

            // issue next step's h loads: 32 slices, 4 commit groups
            const uint4* hsrc = g_hfh + ((1 - p) * 2 + dir) * 8192
                              + bhalf * 128 + tid;
            #pragma unroll
            for (int g4 = 0; g4 < 4; g4++) {
                #pragma unroll
                for (int k8 = 0; k8 < 8; k8++) {
                    int ks = g4 * 8 + k8;
                    cp_async16(hs_addr + (unsigned)ks * 2048, hsrc + ks * 256);
                }
                cp_commit();
            }
        }
        p ^= 1;
    }
}

// ---------------- launch ------------------------------------------------------
extern "C" void kernel_launch(void* const* d_in, const int* in_sizes, int n_in,
                              void* d_out, int out_size)
{
    (void)in_sizes; (void)n_in; (void)out_size;
    const float* x  = (const float*)d_in[0];
    const float* Wx = (const float*)d_in[1];
    const float* Wh = (const float*)d_in[2];
    const float* b  = (const float*)d_in[3];
    float* out = (float*)d_out;

    // idempotent, capture-legal; no static guards (harness rule)
    cudaFuncSetAttribute(scan_kernel,
                         cudaFuncAttributeMaxDynamicSharedMemorySize, SCAN_SMEM);

    dim3 gc(256, 2);
    dim3 gs(32, 2, 2);

    conv_kernel<<<gc, 128>>>(x);
    scan_kernel<<<gs, 128, SCAN_SMEM>>>(Wh, Wx, b, 0, 0, out);
    scan_kernel<<<gs, 128, SCAN_SMEM>>>(Wh, Wx, b, 1, 1, out);
}

// round 14
// speedup vs baseline: 1.5668x; 1.2307x over previous
#include <cuda_runtime.h>
#include <cuda_fp16.h>
#include <math.h>

#define B_   128
#define T_   256
#define H_   512
#define G4_  2048   // 4*H

// ---------------- scratch (device globals; no allocation allowed) -------------
__device__ uint4    g_xf[2097152];      // x as fp16 A-frags [t][ks][rt][lane]
__device__ uint4    g_if[4194304];      // layer-0 out frags [dir][t][ks][rt][lane]
__device__ uint4    g_hfh[32768];       // h ping-pong frags [pp][dir][ks][rt][lane]
__device__ unsigned g_arrive[4];        // cumulative, zero-init  [dir*2+bhalf]
__device__ unsigned g_gen[4];           // cumulative, zero-init

// ---------------- helpers ----------------------------------------------------
__device__ __forceinline__ void mma16(float* c, const uint4& a, const uint2& b) {
    asm volatile(
        "mma.sync.aligned.m16n8k16.row.col.f32.f16.f16.f32 "
        "{%0,%1,%2,%3}, {%4,%5,%6,%7}, {%8,%9}, {%0,%1,%2,%3};\n"
        : "+f"(c[0]), "+f"(c[1]), "+f"(c[2]), "+f"(c[3])
        : "r"(a.x), "r"(a.y), "r"(a.z), "r"(a.w), "r"(b.x), "r"(b.y));
}

__device__ __forceinline__ unsigned packh2(float lo, float hi) {
    __half2 h = __halves2half2(__float2half_rn(lo), __float2half_rn(hi));
    return *reinterpret_cast<unsigned*>(&h);
}

__device__ __forceinline__ float sigm(float x) {
    return 1.f / (1.f + __expf(-x));
}
__device__ __forceinline__ float tanh_(float x) {
    float e = __expf(2.f * x);
    return 1.f - 2.f / (e + 1.f);
}

__device__ __forceinline__ void cp_async16(unsigned smem_addr, const void* gptr) {
    asm volatile("cp.async.cg.shared.global [%0], [%1], 16;\n"
                 :: "r"(smem_addr), "l"(gptr));
}
__device__ __forceinline__ void cp_commit() {
    asm volatile("cp.async.commit_group;\n");
}
template<int N> __device__ __forceinline__ void cp_wait() {
    asm volatile("cp.async.wait_group %0;\n" :: "n"(N));
}

// ---------------- x -> fp16 A-fragment conversion -----------------------------
__global__ void __launch_bounds__(128) conv_kernel(const float* __restrict__ x)
{
    const int t = blockIdx.x, bhalf = blockIdx.y;
    const int tid = threadIdx.x, lane = tid & 31, warp = tid >> 5;
    const int rt = bhalf * 4 + warp;
    const int r  = rt * 16 + (lane >> 2);
    const int k0 = 2 * (lane & 3);
    const float* xr0 = x + ((size_t)r * 256 + t) * 512;
    const float* xr1 = x + ((size_t)(r + 8) * 256 + t) * 512;
    uint4* dst = g_xf + (size_t)t * 8192 + rt * 32 + lane;
    #pragma unroll 4
    for (int ks = 0; ks < 32; ks++) {
        int kk = ks * 16 + k0;
        float2 a0 = *reinterpret_cast<const float2*>(xr0 + kk);
        float2 a1 = *reinterpret_cast<const float2*>(xr1 + kk);
        float2 a2 = *reinterpret_cast<const float2*>(xr0 + kk + 8);
        float2 a3 = *reinterpret_cast<const float2*>(xr1 + kk + 8);
        uint4 fr;
        fr.x = packh2(a0.x, a0.y);
        fr.y = packh2(a1.x, a1.y);
        fr.z = packh2(a2.x, a2.y);
        fr.w = packh2(a3.x, a3.y);
        dst[ks * 256] = fr;
    }
}

// ---------------- warp-specialized persistent scan ----------------------------
// grid (32, 2, 2) x 256 threads. Warps 0-3 (h-warps): recurrence serial chain.
// Warps 4-7 (x-warps): input projection for step s+1 into smem ring XP[2].
// Exactly ONE __syncthreads per step in BOTH roles + one pre-loop sync:
// complete full/empty protocol for the 2-deep ring (no count mismatch).
// smem: Whb 64K | Wxb 64K | hstage 64K | XP 32K = 224 KB.
#define SCAN_SMEM (65536 * 3 + 32768)

__global__ void __launch_bounds__(256, 1) scan_kernel(
    const float* __restrict__ Wh_all, const float* __restrict__ Wx_all,
    const float* __restrict__ bias, int layer, int last, float* __restrict__ out)
{
    extern __shared__ char smbase[];
    uint2*  Whb = reinterpret_cast<uint2*>(smbase);
    uint2*  Wxb = reinterpret_cast<uint2*>(smbase + 65536);
    uint4*  hst = reinterpret_cast<uint4*>(smbase + 131072);   // [ks(32)][tl(128)]
    float4* XP  = reinterpret_cast<float4*>(smbase + 196608);  // [ph(2)][q(8)][tl(128)]

    const int tid  = threadIdx.x;
    const int lane = tid & 31, warp = tid >> 5;
    const bool is_h = warp < 4;
    const int wl = warp & 3;
    const int tl = (wl << 5) | lane;
    const int slice = blockIdx.x;
    const int bhalf = blockIdx.y;
    const int dir   = blockIdx.z;
    const int grp   = dir * 2 + bhalf;
    const int j0    = slice * 16;
    const int rt    = bhalf * 4 + wl;
    const float* Wh = Wh_all + (size_t)(layer * 2 + dir) * H_ * G4_;
    const float* Wx = Wx_all + (size_t)(layer * 2 + dir) * H_ * G4_;
    const float* bs = bias   + (layer * 2 + dir) * G4_;
    const uint4* xfrag = layer ? (g_if + (size_t)dir * 2097152) : g_xf;

    __shared__ unsigned s_genbase;
    if (tid == 0) s_genbase = *((volatile unsigned*)&g_gen[grp]);

    for (int idx = tid; idx < 8192; idx += 256) {
        int l  = idx & 31;
        int q  = idx >> 5;
        int nt = q & 1, g = (q >> 1) & 3, ks = q >> 3;
        int k0 = ks * 16 + 2 * (l & 3);
        int n  = g * 512 + j0 + nt * 8 + (l >> 2);
        Whb[idx] = make_uint2(
            packh2(Wh[(size_t)k0 * 2048 + n], Wh[(size_t)(k0 + 1) * 2048 + n]),
            packh2(Wh[(size_t)(k0 + 8) * 2048 + n], Wh[(size_t)(k0 + 9) * 2048 + n]));
        Wxb[idx] = make_uint2(
            packh2(Wx[(size_t)k0 * 2048 + n], Wx[(size_t)(k0 + 1) * 2048 + n]),
            packh2(Wx[(size_t)(k0 + 8) * 2048 + n], Wx[(size_t)(k0 + 9) * 2048 + n]));
    }
    __syncthreads();
    const unsigned gen_base = s_genbase;

    const int row_base = rt * 16 + (lane >> 2);
    const int u2 = 2 * (lane & 3);
    const unsigned hs_addr =
        (unsigned)__cvta_generic_to_shared(hst) + (unsigned)tl * 16;

    float creg[2][4] = {{0.f,0.f,0.f,0.f},{0.f,0.f,0.f,0.f}};
    int p = 0;

    if (is_h) {
        __syncthreads();   // matches producer's post-XP[0] sync
        #pragma unroll 1
        for (int s = 0; s < 256; s++) {
            const int t = (dir == 0) ? s : (255 - s);

            float acc[4][2][4];
            #pragma unroll
            for (int g = 0; g < 4; g++)
                #pragma unroll
                for (int nt = 0; nt < 2; nt++)
                    #pragma unroll
                    for (int k = 0; k < 4; k++) acc[g][nt][k] = 0.f;

            if (s > 0) {
                #pragma unroll
                for (int g4 = 0; g4 < 4; g4++) {
                    if      (g4 == 0) cp_wait<3>();
                    else if (g4 == 1) cp_wait<2>();
                    else if (g4 == 2) cp_wait<1>();
                    else              cp_wait<0>();
                    #pragma unroll
                    for (int k8 = 0; k8 < 8; k8++) {
                        int ks = g4 * 8 + k8;
                        uint4 a = hst[ks * 128 + tl];
                        #pragma unroll
                        for (int g = 0; g < 4; g++)
                            #pragma unroll
                            for (int nt = 0; nt < 2; nt++)
                                mma16(acc[g][nt], a,
                                      Whb[((ks * 4 + g) * 2 + nt) * 32 + lane]);
                    }
                }
            }

            float4 xpv[8];
            #pragma unroll
            for (int q = 0; q < 8; q++)
                xpv[q] = XP[(s & 1) * 1024 + q * 128 + tl];

            float hn[2][4];
            #pragma unroll
            for (int nt = 0; nt < 2; nt++)
                #pragma unroll
                for (int k = 0; k < 4; k++) {
                    const float* pi = &xpv[0 * 2 + nt].x;
                    const float* pf = &xpv[1 * 2 + nt].x;
                    const float* pg = &xpv[2 * 2 + nt].x;
                    const float* po = &xpv[3 * 2 + nt].x;
                    float i_ = sigm(acc[0][nt][k] + pi[k]);
                    float f_ = sigm(acc[1][nt][k] + pf[k]);
                    float gg = tanh_(acc[2][nt][k] + pg[k]);
                    float o_ = sigm(acc[3][nt][k] + po[k]);
                    float cn = f_ * creg[nt][k] + i_ * gg;
                    creg[nt][k] = cn;
                    hn[nt][k] = o_ * tanh_(cn);
                }

            uint4 fr;
            fr.x = packh2(hn[0][0], hn[0][1]);
            fr.y = packh2(hn[0][2], hn[0][3]);
            fr.z = packh2(hn[1][0], hn[1][1]);
            fr.w = packh2(hn[1][2], hn[1][3]);

            if (s < 255)
                g_hfh[((1 - p) * 2 + dir) * 8192 + slice * 256 + rt * 32 + lane] = fr;

            if (!last) {
                g_if[(size_t)dir * 2097152 + (size_t)t * 8192
                     + slice * 256 + rt * 32 + lane] = fr;
            } else {
                #pragma unroll
                for (int nt = 0; nt < 2; nt++)
                    #pragma unroll
                    for (int rr = 0; rr < 2; rr++) {
                        int r = row_base + rr * 8;
                        int u = j0 + nt * 8 + u2;
                        *reinterpret_cast<float2*>(
                            out + ((size_t)r * 256 + t) * 1024 + dir * 512 + u) =
                            make_float2(hn[nt][rr * 2], hn[nt][rr * 2 + 1]);
                    }
            }

            if (s < 255) {
                if (tid == 0) {
                    __threadfence();
                    unsigned old = atomicAdd(&g_arrive[grp], 1u);
                    if ((old & 31u) == 31u) {
                        __threadfence();
                        atomicAdd(&g_gen[grp], 1u);
                    }
                }
                {
                    unsigned target = gen_base + (unsigned)(s + 1);
                    while ((int)(*((volatile unsigned*)&g_gen[grp]) - target) < 0) {}
                }
                const uint4* hsrc = g_hfh + ((1 - p) * 2 + dir) * 8192
                                  + bhalf * 128 + tl;
                #pragma unroll
                for (int g4 = 0; g4 < 4; g4++) {
                    #pragma unroll
                    for (int k8 = 0; k8 < 8; k8++) {
                        int ks = g4 * 8 + k8;
                        cp_async16(hs_addr + (unsigned)ks * 2048, hsrc + ks * 256);
                    }
                    cp_commit();
                }
            }
            __syncthreads();   // per-step meet with producers (ring flip)
            p ^= 1;
        }
    } else {
        float2 bias2[4][2];
        #pragma unroll
        for (int g = 0; g < 4; g++)
            #pragma unroll
            for (int nt = 0; nt < 2; nt++)
                bias2[g][nt] = *reinterpret_cast<const float2*>(
                    bs + g * 512 + j0 + nt * 8 + u2);

        auto xphase = [&](int tn, int ph) {
            const uint4* xs = xfrag + (size_t)tn * 8192 + rt * 32 + lane;
            float pvacc[4][2][4];
            uint4 xb[8];
            #pragma unroll
            for (int i = 0; i < 8; i++) xb[i] = xs[i * 256];
            #pragma unroll
            for (int g = 0; g < 4; g++)
                #pragma unroll
                for (int nt = 0; nt < 2; nt++) {
                    pvacc[g][nt][0] = bias2[g][nt].x;
                    pvacc[g][nt][1] = bias2[g][nt].y;
                    pvacc[g][nt][2] = bias2[g][nt].x;
                    pvacc[g][nt][3] = bias2[g][nt].y;
                }
            #pragma unroll
            for (int ks = 0; ks < 32; ks++) {
                uint4 a = xb[ks & 7];
                if (ks < 24) xb[ks & 7] = xs[(ks + 8) * 256];
                #pragma unroll
                for (int g = 0; g < 4; g++)
                    #pragma unroll
                    for (int nt = 0; nt < 2; nt++)
                        mma16(pvacc[g][nt], a,
                              Wxb[((ks * 4 + g) * 2 + nt) * 32 + lane]);
            }
            #pragma unroll
            for (int g = 0; g < 4; g++)
                #pragma unroll
                for (int nt = 0; nt < 2; nt++)
                    XP[ph * 1024 + (g * 2 + nt) * 128 + tl] =
                        make_float4(pvacc[g][nt][0], pvacc[g][nt][1],
                                    pvacc[g][nt][2], pvacc[g][nt][3]);
        };

        xphase((dir == 0) ? 0 : 255, 0);   // fill XP[0] for step 0
        __syncthreads();                   // release XP[0] (matches consumer)
        #pragma unroll 1
        for (int s = 0; s < 256; s++) {
            if (s < 255)
                xphase((dir == 0) ? (s + 1) : (254 - s), (s + 1) & 1);
            __syncthreads();               // per-step meet with consumers
        }
    }
}

// ---------------- launch ------------------------------------------------------
extern "C" void kernel_launch(void* const* d_in, const int* in_sizes, int n_in,
                              void* d_out, int out_size)
{
    (void)in_sizes; (void)n_in; (void)out_size;
    const float* x  = (const float*)d_in[0];
    const float* Wx = (const float*)d_in[1];
    const float* Wh = (const float*)d_in[2];
    const float* b  = (const float*)d_in[3];
    float* out = (float*)d_out;

    // idempotent, capture-legal; no static guards (harness rule)
    cudaFuncSetAttribute(scan_kernel,
                         cudaFuncAttributeMaxDynamicSharedMemorySize, SCAN_SMEM);

    dim3 gc(256, 2);
    dim3 gs(32, 2, 2);

    conv_kernel<<<gc, 128>>>(x);
    scan_kernel<<<gs, 256, SCAN_SMEM>>>(Wh, Wx, b, 0, 0, out);
    scan_kernel<<<gs, 256, SCAN_SMEM>>>(Wh, Wx, b, 1, 1, out);
}